// round 10
// baseline (speedup 1.0000x reference)
#include <cuda_runtime.h>
#include <math.h>

#define IMG 96
#define NT  256

// ---- smem layout (float word offsets) ----
#define O_XS    0                 // xs: 32ch x 4 rows x 34 cols, ch stride 137
#define XS_CST  137
#define XS_RST  34
#define O_PHI   4384              // phi chunk: 72 k-rows x 64 d; later alphaT (64x68)
#define O_HS    8992              // h: 64 px x 66
#define HS_ST   66
#define O_ST    13216             // stats: 64 x 6 ([5] = phi_b dot patch)
#define O_PROJ  13600
#define O_FC1W  13664
#define O_FC1B  13984
#define O_PHIB  14048
#define O_ALB   14336
#define O_BNI   14400
#define O_BNM   14464
#define O_BNB   14528
#define SMEM_F  14592             // 58368 B -> 3 blocks/SM (24 warps)

#define PK2(d, lo, hi) asm("mov.b64 %0, {%1, %2};" : "=l"(d) : "r"(lo), "r"(hi))
#define UPK2(lo, hi, v) asm("mov.b64 {%0, %1}, %2;" : "=r"(lo), "=r"(hi) : "l"(v))
#define FMA2(d, a, b) asm("fma.rn.f32x2 %0, %1, %2, %3;" : "=l"(d) : "l"(a), "l"(b), "l"(d))

__global__ __launch_bounds__(NT, 3) void sac_kernel(
    const float* __restrict__ x,       const float* __restrict__ fc1_w,
    const float* __restrict__ fc1_b,   const float* __restrict__ alpha_w,
    const float* __restrict__ alpha_b, const float* __restrict__ phi_w,
    const float* __restrict__ phi_b,   const float* __restrict__ bn_g,
    const float* __restrict__ bn_b,    const float* __restrict__ bn_m,
    const float* __restrict__ bn_v,    float* __restrict__ out)
{
    extern __shared__ float sm[];
    const int t  = threadIdx.x;
    const int jt = blockIdx.x;          // 3 col tiles of 32
    const int it = blockIdx.y;          // 48 row tiles of 2
    const int bz = blockIdx.z;
    const int j0 = jt * 32;

    // ---------------- Phase 0: stage ----------------
    for (int idx = t; idx < 32 * 136; idx += NT) {     // 4 rows x 34 cols per ch
        int c = idx / 136, rem = idx - c * 136;
        int r = rem / 34,  cc = rem - r * 34;
        int gr = it * 2 - 1 + r, gc = j0 - 1 + cc;
        float v = 0.f;
        if ((unsigned)gr < IMG && (unsigned)gc < IMG)
            v = x[((bz * 32 + c) * IMG + gr) * IMG + gc];
        sm[O_XS + c * XS_CST + r * XS_RST + cc] = v;
    }
    for (int idx = t; idx < 320; idx += NT) sm[O_FC1W + idx] = fc1_w[idx];
    for (int idx = t; idx < 288; idx += NT) sm[O_PHIB + idx] = phi_b[idx];
    if (t < 64) {
        sm[O_FC1B + t] = fc1_b[t];
        sm[O_ALB  + t] = alpha_b[t];
        sm[O_BNI  + t] = bn_g[t] * rsqrtf(bn_v[t] + 1e-5f);
        sm[O_BNM  + t] = bn_m[t];
        sm[O_BNB  + t] = bn_b[t];
    }
    __syncthreads();

    // ---------------- Phase A: stats, 8 thr/px, 2 passes of 32 px ----------------
    {
        const int sub = t & 7;
        #pragma unroll 1
        for (int p4 = 0; p4 < 2; p4++) {
            const int pxl = p4 * 32 + (t >> 3);
            const int rr = pxl >> 5, ca = pxl & 31;
            float v[36];
            float s0 = 0.f, mn = 3.4e38f, mx = -3.4e38f, pb = 0.f;
            #pragma unroll
            for (int cc = 0; cc < 4; cc++) {
                const int c = sub + cc * 8;
                const float* xb = sm + O_XS + c * XS_CST + rr * XS_RST + ca;
                const float* pbb = sm + O_PHIB + c * 9;
                #pragma unroll
                for (int kh = 0; kh < 3; kh++)
                    #pragma unroll
                    for (int kw = 0; kw < 3; kw++) {
                        float val = xb[kh * XS_RST + kw];
                        v[cc * 9 + kh * 3 + kw] = val;
                        s0 += val;
                        mn = fminf(mn, val);
                        mx = fmaxf(mx, val);
                        pb += pbb[kh * 3 + kw] * val;
                    }
            }
            #pragma unroll
            for (int m = 1; m < 8; m <<= 1) {
                s0 += __shfl_xor_sync(0xffffffffu, s0, m);
                pb += __shfl_xor_sync(0xffffffffu, pb, m);
                mn = fminf(mn, __shfl_xor_sync(0xffffffffu, mn, m));
                mx = fmaxf(mx, __shfl_xor_sync(0xffffffffu, mx, m));
            }
            const float mu  = s0 * (1.f / 288.f);
            const float rng = mx - mn + 1e-6f;
            const float s15 = __fdiv_rn(15.f, rng);
            float sd2 = 0.f;
            unsigned long long hl = 0ull, hh = 0ull;
            #pragma unroll
            for (int i = 0; i < 36; i++) {
                float d = v[i] - mu;
                sd2 += d * d;
                float dmn = v[i] - mn;
                float y = dmn * s15;
                int b = (int)y;
                float fb = (float)b;
                float eps = y * 1.2e-6f + 1e-35f;
                if (y - fb < eps || (fb + 1.0f) - y < eps)
                    b = (int)(__fdiv_rn(dmn, rng) * 15.0f);   // exact reference path
                b = min(b, 15);
                unsigned long long one = 1ull << ((b & 7) * 8);
                hl += (b < 8) ? one : 0ull;
                hh += (b < 8) ? 0ull : one;
            }
            #pragma unroll
            for (int m = 1; m < 8; m <<= 1) sd2 += __shfl_xor_sync(0xffffffffu, sd2, m);
            const float var   = sd2 * (1.f / 288.f);
            const float sigma = __fsqrt_rn(var + 1e-6f);
            const float zinv  = __fdiv_rn(1.f, sigma + 1e-6f);
            float s3 = 0.f, s4 = 0.f;
            #pragma unroll
            for (int i = 0; i < 36; i++) {
                float z = (v[i] - mu) * zinv, z2 = z * z;
                s3 += z2 * z;
                s4 += z2 * z2;
            }
            const unsigned long long M8 = 0x00FF00FF00FF00FFull;
            unsigned long long wl0 = hl & M8, wl1 = (hl >> 8) & M8;
            unsigned long long wh0 = hh & M8, wh1 = (hh >> 8) & M8;
            #pragma unroll
            for (int m = 1; m < 8; m <<= 1) {
                s3  += __shfl_xor_sync(0xffffffffu, s3, m);
                s4  += __shfl_xor_sync(0xffffffffu, s4, m);
                wl0 += __shfl_xor_sync(0xffffffffu, wl0, m);
                wl1 += __shfl_xor_sync(0xffffffffu, wl1, m);
                wh0 += __shfl_xor_sync(0xffffffffu, wh0, m);
                wh1 += __shfl_xor_sync(0xffffffffu, wh1, m);
            }
            // entropy: 2 bins per lane
            unsigned long long wa = (sub & 2) ? wl1 : wl0;
            unsigned long long wb = (sub & 2) ? wh1 : wh0;
            unsigned long long w  = (sub & 4) ? wb : wa;
            unsigned c0 = (unsigned)(w >> ((sub & 1) * 32)) & 0xFFFFu;
            unsigned c1 = (unsigned)(w >> ((sub & 1) * 32 + 16)) & 0xFFFFu;
            float p0 = (float)c0 * (1.f / 288.f), p1 = (float)c1 * (1.f / 288.f);
            float ent = -(p0 * __logf(p0 + 1e-9f) + p1 * __logf(p1 + 1e-9f));
            #pragma unroll
            for (int m = 1; m < 8; m <<= 1) ent += __shfl_xor_sync(0xffffffffu, ent, m);
            if (sub == 0) {
                sm[O_ST + pxl * 6 + 0] = mu;
                sm[O_ST + pxl * 6 + 1] = sigma;
                sm[O_ST + pxl * 6 + 2] = s3 * (1.f / 288.f);
                sm[O_ST + pxl * 6 + 3] = s4 * (1.f / 288.f) - 3.0f;
                sm[O_ST + pxl * 6 + 4] = ent;
                sm[O_ST + pxl * 6 + 5] = pb;
            }
        }
    }
    __syncthreads();

    // ---------------- Phase B: h = relu(fc1(s)), 4 thr/px ----------------
    {
        const int px = t >> 2, db = (t & 3) * 16;
        const float s0 = sm[O_ST + px * 6 + 0], s1 = sm[O_ST + px * 6 + 1],
                    s2 = sm[O_ST + px * 6 + 2], s3 = sm[O_ST + px * 6 + 3],
                    s4 = sm[O_ST + px * 6 + 4];
        #pragma unroll 4
        for (int dd = 0; dd < 16; dd++) {
            int d = db + dd;
            const float* wp = sm + O_FC1W + d * 5;
            float a = sm[O_FC1B + d] + s0 * wp[0] + s1 * wp[1] + s2 * wp[2]
                      + s3 * wp[3] + s4 * wp[4];
            sm[O_HS + px * HS_ST + d] = fmaxf(a, 0.f);
        }
    }

    // ---------------- Phase C: q-GEMM 64px x 64d x 288k ----------------
    // lane dg owns d-pairs (B loads natural u64, zero packs); A dup'd in regs (6 PK2/(c,kh))
    const int dg = t & 15, pg = t >> 4;
    const int d0 = dg * 4;                 // 4 d = 2 pairs
    const int rr = pg >> 3, cp4 = (pg & 7) * 4;  // 4 px: cols cp4..cp4+3, row rr
    unsigned long long acc[2][4];
    #pragma unroll
    for (int q = 0; q < 2; q++)
        #pragma unroll
        for (int p = 0; p < 4; p++) acc[q][p] = 0ull;

    #pragma unroll 1
    for (int seg = 0; seg < 4; seg++) {
        __syncthreads();
        {   // stage phi k-rows [seg*72, seg*72+72)
            const float4* pw4 = (const float4*)phi_w;
            float4* ps4 = (float4*)(sm + O_PHI);
            #pragma unroll
            for (int i = 0; i < 5; i++) {
                int idx = t + i * NT;
                if (idx < 1152) ps4[idx] = pw4[seg * 1152 + idx];
            }
        }
        __syncthreads();
        #pragma unroll 1
        for (int cl = 0; cl < 8; cl++) {
            const float* xc = sm + O_XS + (seg * 8 + cl) * XS_CST + rr * XS_RST + cp4;
            #pragma unroll
            for (int kh = 0; kh < 3; kh++) {
                const float* xr = xc + kh * XS_RST;
                unsigned long long ad[6];
                #pragma unroll
                for (int j = 0; j < 6; j++) {
                    unsigned u = __float_as_uint(xr[j]);
                    PK2(ad[j], u, u);
                }
                const float* bb = sm + O_PHI + (cl * 9 + kh * 3) * 64 + d0;
                #pragma unroll
                for (int kw = 0; kw < 3; kw++) {
                    const ulonglong2 b = *(const ulonglong2*)(bb + kw * 64);
                    #pragma unroll
                    for (int p = 0; p < 4; p++) {
                        FMA2(acc[0][p], ad[p + kw], b.x);
                        FMA2(acc[1][p], ad[p + kw], b.y);
                    }
                }
            }
        }
    }
    // epilogue: proj = h.q + phi_b.patch (16-lane reduce within half-warp)
    {
        #pragma unroll
        for (int p = 0; p < 4; p++) {
            const int pxl = rr * 32 + cp4 + p;
            const unsigned long long h0 = *(const unsigned long long*)
                (sm + O_HS + pxl * HS_ST + d0);
            const unsigned long long h1 = *(const unsigned long long*)
                (sm + O_HS + pxl * HS_ST + d0 + 2);
            unsigned long long s = 0ull;
            FMA2(s, acc[0][p], h0);
            FMA2(s, acc[1][p], h1);
            unsigned lo, hi;
            UPK2(lo, hi, s);
            float part = __uint_as_float(lo) + __uint_as_float(hi);
            #pragma unroll
            for (int m = 1; m < 16; m <<= 1)
                part += __shfl_xor_sync(0xffffffffu, part, m);
            if (dg == 0) sm[O_PROJ + pxl] = part + sm[O_ST + pxl * 6 + 5];
        }
    }
    __syncthreads();

    // stage alpha_w^T into dead phi area (stride 68)
    for (int idx = t; idx < 64 * 64; idx += NT) {
        int c = idx >> 6, d = idx & 63;
        sm[O_PHI + d * 68 + c] = alpha_w[idx];
    }
    __syncthreads();

    // ---------------- Phase D: alpha GEMV (c-pair f32x2) + BN + SiLU ----------------
    {
        const int px = t >> 2, cq = t & 3;
        const int c0 = cq * 16;                    // 16 c = 8 pairs
        unsigned long long ac[8];
        #pragma unroll
        for (int i = 0; i < 8; i++) ac[i] = 0ull;
        #pragma unroll 4
        for (int d = 0; d < 64; d++) {
            float h = sm[O_HS + px * HS_ST + d];
            unsigned long long hd;
            unsigned hu = __float_as_uint(h);
            PK2(hd, hu, hu);
            const float* wb = sm + O_PHI + d * 68 + c0;
            #pragma unroll
            for (int i = 0; i < 4; i++) {
                const ulonglong2 w = *(const ulonglong2*)(wb + i * 4);
                FMA2(ac[2 * i + 0], hd, w.x);
                FMA2(ac[2 * i + 1], hd, w.y);
            }
        }
        const float prj = sm[O_PROJ + px];
        const int row  = it * 2 + (px >> 5);
        const int gcol = j0 + (px & 31);
        #pragma unroll
        for (int i = 0; i < 8; i++) {
            unsigned u0, u1;
            UPK2(u0, u1, ac[i]);
            #pragma unroll
            for (int s2 = 0; s2 < 2; s2++) {
                const int c = c0 + 2 * i + s2;
                float al = __uint_as_float(s2 ? u1 : u0) + sm[O_ALB + c];
                float y  = (al * prj - sm[O_BNM + c]) * sm[O_BNI + c] + sm[O_BNB + c];
                float r  = y * __fdividef(1.f, 1.f + __expf(-y));
                out[((bz * 64 + c) * IMG + row) * IMG + gcol] = r;
            }
        }
    }
}

extern "C" void kernel_launch(void* const* d_in, const int* in_sizes, int n_in,
                              void* d_out, int out_size) {
    cudaFuncSetAttribute(sac_kernel, cudaFuncAttributeMaxDynamicSharedMemorySize,
                         SMEM_F * sizeof(float));
    dim3 grid(3, 48, 4);
    sac_kernel<<<grid, NT, SMEM_F * sizeof(float)>>>(
        (const float*)d_in[0],  (const float*)d_in[1], (const float*)d_in[2],
        (const float*)d_in[3],  (const float*)d_in[4], (const float*)d_in[5],
        (const float*)d_in[6],  (const float*)d_in[7], (const float*)d_in[8],
        (const float*)d_in[9],  (const float*)d_in[10], (float*)d_out);
}

// round 11
// speedup vs baseline: 1.3021x; 1.3021x over previous
#include <cuda_runtime.h>
#include <math.h>

#define IMG 96
#define NT  256

// ---- smem layout (float word offsets) ----
#define O_XS    0                 // xs: 32ch x 6 rows x 36 cols, ch stride 217
#define XS_CS   217
#define XS_RS   36
#define O_PHI   6944              // phi chunk: 144 k-rows x 64 d; later alphaT (64x68)
#define O_HS    16160             // h: 128 px x 66
#define HS_ST   66
#define O_ST    24608             // stats: 128 x 6 ([5] = phi_b dot patch)
#define O_PROJ  25376
#define O_FC1W  25504
#define O_FC1B  25824
#define O_PHIB  25888
#define O_ALB   26176
#define O_BNI   26240
#define O_BNM   26304
#define O_BNB   26368
#define SMEM_F  26432             // 105728 B -> 2 blocks/SM, single wave @ 288 blocks

#define PK2(d, lo, hi) asm("mov.b64 %0, {%1, %2};" : "=l"(d) : "r"(lo), "r"(hi))
#define UPK2(lo, hi, v) asm("mov.b64 {%0, %1}, %2;" : "=r"(lo), "=r"(hi) : "l"(v))
#define FMA2(d, a, b) asm("fma.rn.f32x2 %0, %1, %2, %3;" : "=l"(d) : "l"(a), "l"(b), "l"(d))

__global__ __launch_bounds__(NT, 2) void sac_kernel(
    const float* __restrict__ x,       const float* __restrict__ fc1_w,
    const float* __restrict__ fc1_b,   const float* __restrict__ alpha_w,
    const float* __restrict__ alpha_b, const float* __restrict__ phi_w,
    const float* __restrict__ phi_b,   const float* __restrict__ bn_g,
    const float* __restrict__ bn_b,    const float* __restrict__ bn_m,
    const float* __restrict__ bn_v,    float* __restrict__ out)
{
    extern __shared__ float sm[];
    const int t  = threadIdx.x;
    const int jt = blockIdx.x;          // 3 col tiles of 32
    const int it = blockIdx.y;          // 24 row tiles of 4
    const int bz = blockIdx.z;
    const int j0 = jt * 32;
    float* xs = sm + O_XS;

    // ---------------- Phase 0: stage ----------------
    for (int idx = t; idx < 32 * 216; idx += NT) {
        int c = idx / 216, rem = idx - c * 216;
        int r = rem / 36, col = rem - r * 36;
        int gr = it * 4 - 1 + r, gc = j0 - 1 + col;
        float v = 0.f;
        if (col < 34 && (unsigned)gr < IMG && (unsigned)gc < IMG)
            v = x[((bz * 32 + c) * IMG + gr) * IMG + gc];
        xs[c * XS_CS + r * XS_RS + col] = v;
    }
    {   // phi k-rows [0,144)
        const float4* pw4 = (const float4*)phi_w;
        float4* ps4 = (float4*)(sm + O_PHI);
        for (int idx = t; idx < 2304; idx += NT) ps4[idx] = pw4[idx];
    }
    for (int idx = t; idx < 320; idx += NT) sm[O_FC1W + idx] = fc1_w[idx];
    for (int idx = t; idx < 288; idx += NT) sm[O_PHIB + idx] = phi_b[idx];
    if (t < 64) {
        sm[O_FC1B + t] = fc1_b[t];
        sm[O_ALB  + t] = alpha_b[t];
        sm[O_BNI  + t] = bn_g[t] * rsqrtf(bn_v[t] + 1e-5f);
        sm[O_BNM  + t] = bn_m[t];
        sm[O_BNB  + t] = bn_b[t];
    }
    __syncthreads();

    // ---------------- Phase A: stats, 8 thr/px, 4 passes of 32 px ----------------
    {
        const int sub = t & 7;
        #pragma unroll 1
        for (int p4 = 0; p4 < 4; p4++) {
            const int pxl = p4 * 32 + (t >> 3);
            const int ra = pxl >> 5, ca = pxl & 31;
            float v[36];
            float s0 = 0.f, mn = 3.4e38f, mx = -3.4e38f, pb = 0.f;
            #pragma unroll
            for (int cc = 0; cc < 4; cc++) {
                const int c = sub + cc * 8;
                const float* xb = xs + c * XS_CS + ra * XS_RS + ca;
                const float* pbb = sm + O_PHIB + c * 9;
                #pragma unroll
                for (int kh = 0; kh < 3; kh++)
                    #pragma unroll
                    for (int kw = 0; kw < 3; kw++) {
                        float val = xb[kh * XS_RS + kw];
                        v[cc * 9 + kh * 3 + kw] = val;
                        s0 += val;
                        mn = fminf(mn, val);
                        mx = fmaxf(mx, val);
                        pb += pbb[kh * 3 + kw] * val;
                    }
            }
            #pragma unroll
            for (int m = 1; m < 8; m <<= 1) {
                s0 += __shfl_xor_sync(0xffffffffu, s0, m);
                pb += __shfl_xor_sync(0xffffffffu, pb, m);
                mn = fminf(mn, __shfl_xor_sync(0xffffffffu, mn, m));
                mx = fmaxf(mx, __shfl_xor_sync(0xffffffffu, mx, m));
            }
            const float mu  = s0 * (1.f / 288.f);
            const float rng = mx - mn + 1e-6f;
            const float s15 = __fdiv_rn(15.f, rng);
            float sd2 = 0.f;
            unsigned long long hl = 0ull, hh = 0ull;
            #pragma unroll
            for (int i = 0; i < 36; i++) {
                float d = v[i] - mu;
                sd2 += d * d;
                float dmn = v[i] - mn;
                float y = dmn * s15;
                int b = (int)y;
                float fb = (float)b;
                float eps = y * 1.2e-6f + 1e-35f;
                if (y - fb < eps || (fb + 1.0f) - y < eps)
                    b = (int)(__fdiv_rn(dmn, rng) * 15.0f);   // exact reference path
                b = min(b, 15);
                unsigned long long one = 1ull << ((b & 7) * 8);
                hl += (b < 8) ? one : 0ull;
                hh += (b < 8) ? 0ull : one;
            }
            #pragma unroll
            for (int m = 1; m < 8; m <<= 1) sd2 += __shfl_xor_sync(0xffffffffu, sd2, m);
            const float var   = sd2 * (1.f / 288.f);
            const float sigma = __fsqrt_rn(var + 1e-6f);
            const float zinv  = __fdiv_rn(1.f, sigma + 1e-6f);
            float s3 = 0.f, s4 = 0.f;
            #pragma unroll
            for (int i = 0; i < 36; i++) {
                float z = (v[i] - mu) * zinv, z2 = z * z;
                s3 += z2 * z;
                s4 += z2 * z2;
            }
            const unsigned long long M8 = 0x00FF00FF00FF00FFull;
            unsigned long long wl0 = hl & M8, wl1 = (hl >> 8) & M8;
            unsigned long long wh0 = hh & M8, wh1 = (hh >> 8) & M8;
            #pragma unroll
            for (int m = 1; m < 8; m <<= 1) {
                s3  += __shfl_xor_sync(0xffffffffu, s3, m);
                s4  += __shfl_xor_sync(0xffffffffu, s4, m);
                wl0 += __shfl_xor_sync(0xffffffffu, wl0, m);
                wl1 += __shfl_xor_sync(0xffffffffu, wl1, m);
                wh0 += __shfl_xor_sync(0xffffffffu, wh0, m);
                wh1 += __shfl_xor_sync(0xffffffffu, wh1, m);
            }
            // entropy: 2 bins per lane
            unsigned long long wa = (sub & 2) ? wl1 : wl0;
            unsigned long long wb = (sub & 2) ? wh1 : wh0;
            unsigned long long w  = (sub & 4) ? wb : wa;
            unsigned c0 = (unsigned)(w >> ((sub & 1) * 32)) & 0xFFFFu;
            unsigned c1 = (unsigned)(w >> ((sub & 1) * 32 + 16)) & 0xFFFFu;
            float p0 = (float)c0 * (1.f / 288.f), p1 = (float)c1 * (1.f / 288.f);
            float ent = -(p0 * __logf(p0 + 1e-9f) + p1 * __logf(p1 + 1e-9f));
            #pragma unroll
            for (int m = 1; m < 8; m <<= 1) ent += __shfl_xor_sync(0xffffffffu, ent, m);
            if (sub == 0) {
                sm[O_ST + pxl * 6 + 0] = mu;
                sm[O_ST + pxl * 6 + 1] = sigma;
                sm[O_ST + pxl * 6 + 2] = s3 * (1.f / 288.f);
                sm[O_ST + pxl * 6 + 3] = s4 * (1.f / 288.f) - 3.0f;
                sm[O_ST + pxl * 6 + 4] = ent;
                sm[O_ST + pxl * 6 + 5] = pb;
            }
        }
    }
    __syncthreads();

    // ---------------- Phase B: h = relu(fc1(s)), 2 thr/px ----------------
    {
        const int px = t >> 1, db = (t & 1) * 32;
        const float s0 = sm[O_ST + px * 6 + 0], s1 = sm[O_ST + px * 6 + 1],
                    s2 = sm[O_ST + px * 6 + 2], s3 = sm[O_ST + px * 6 + 3],
                    s4 = sm[O_ST + px * 6 + 4];
        #pragma unroll 8
        for (int dd = 0; dd < 32; dd++) {
            int d = db + dd;
            const float* wp = sm + O_FC1W + d * 5;
            float a = sm[O_FC1B + d] + s0 * wp[0] + s1 * wp[1] + s2 * wp[2]
                      + s3 * wp[3] + s4 * wp[4];
            sm[O_HS + px * HS_ST + d] = fmaxf(a, 0.f);
        }
    }
    __syncthreads();

    // ---------------- Phase C: q-GEMM 128px x 64d x 288k, d-pair acc ----------------
    // lane dg owns 4 d (2 natural u64 B pairs, zero B packs); A dup'd in regs
    const int dg = t & 15, pg = t >> 4;
    const int d0 = dg * 4;
    const int rr = pg >> 2, col0 = (pg & 3) * 8;   // 8 px: cols col0..col0+7, row rr
    unsigned long long acc[2][8];
    #pragma unroll
    for (int q = 0; q < 2; q++)
        #pragma unroll
        for (int p = 0; p < 8; p++) acc[q][p] = 0ull;

    {
        const float* xb = xs + rr * XS_RS + col0;
        #pragma unroll 1
        for (int c = 0; c < 16; c++) {
            #pragma unroll
            for (int kh = 0; kh < 3; kh++) {
                const float* xr = xb + c * XS_CS + kh * XS_RS;
                unsigned long long ad[10];
                #pragma unroll
                for (int j = 0; j < 10; j++) {
                    unsigned u = __float_as_uint(xr[j]);
                    PK2(ad[j], u, u);
                }
                const float* bb = sm + O_PHI + (c * 9 + kh * 3) * 64 + d0;
                #pragma unroll
                for (int kw = 0; kw < 3; kw++) {
                    const ulonglong2 b = *(const ulonglong2*)(bb + kw * 64);
                    #pragma unroll
                    for (int p = 0; p < 8; p++) {
                        FMA2(acc[0][p], ad[p + kw], b.x);
                        FMA2(acc[1][p], ad[p + kw], b.y);
                    }
                }
            }
        }
    }
    __syncthreads();
    {   // restage phi k-rows [144,288)
        const float4* pw4 = (const float4*)phi_w;
        float4* ps4 = (float4*)(sm + O_PHI);
        for (int idx = t; idx < 2304; idx += NT) ps4[idx] = pw4[2304 + idx];
    }
    __syncthreads();
    {
        const float* xb = xs + rr * XS_RS + col0;
        #pragma unroll 1
        for (int c = 0; c < 16; c++) {
            #pragma unroll
            for (int kh = 0; kh < 3; kh++) {
                const float* xr = xb + (c + 16) * XS_CS + kh * XS_RS;
                unsigned long long ad[10];
                #pragma unroll
                for (int j = 0; j < 10; j++) {
                    unsigned u = __float_as_uint(xr[j]);
                    PK2(ad[j], u, u);
                }
                const float* bb = sm + O_PHI + (c * 9 + kh * 3) * 64 + d0;
                #pragma unroll
                for (int kw = 0; kw < 3; kw++) {
                    const ulonglong2 b = *(const ulonglong2*)(bb + kw * 64);
                    #pragma unroll
                    for (int p = 0; p < 8; p++) {
                        FMA2(acc[0][p], ad[p + kw], b.x);
                        FMA2(acc[1][p], ad[p + kw], b.y);
                    }
                }
            }
        }
    }
    // epilogue: proj = h.q + phi_b.patch (16-lane reduce over dg)
    {
        #pragma unroll
        for (int p = 0; p < 8; p++) {
            const int pxl = rr * 32 + col0 + p;
            const unsigned long long h0 = *(const unsigned long long*)
                (sm + O_HS + pxl * HS_ST + d0);
            const unsigned long long h1 = *(const unsigned long long*)
                (sm + O_HS + pxl * HS_ST + d0 + 2);
            unsigned long long s = 0ull;
            FMA2(s, acc[0][p], h0);
            FMA2(s, acc[1][p], h1);
            unsigned lo, hi;
            UPK2(lo, hi, s);
            float part = __uint_as_float(lo) + __uint_as_float(hi);
            #pragma unroll
            for (int m = 1; m < 16; m <<= 1)
                part += __shfl_xor_sync(0xffffffffu, part, m);
            if (dg == 0) sm[O_PROJ + pxl] = part + sm[O_ST + pxl * 6 + 5];
        }
    }
    __syncthreads();

    // stage alpha_w^T into dead phi area (stride 68)
    for (int idx = t; idx < 64 * 64; idx += NT) {
        int c = idx >> 6, d = idx & 63;
        sm[O_PHI + d * 68 + c] = alpha_w[idx];
    }
    __syncthreads();

    // ---------------- Phase D: alpha GEMV (c-pair f32x2) + BN + SiLU ----------------
    {
        const int px = t >> 1, cq = t & 1;
        const int c0 = cq * 32;                    // 32 c = 16 pairs
        unsigned long long ac[16];
        #pragma unroll
        for (int i = 0; i < 16; i++) ac[i] = 0ull;
        #pragma unroll 4
        for (int d = 0; d < 64; d++) {
            float h = sm[O_HS + px * HS_ST + d];
            unsigned long long hd;
            unsigned hu = __float_as_uint(h);
            PK2(hd, hu, hu);
            const float* wb = sm + O_PHI + d * 68 + c0;
            #pragma unroll
            for (int i = 0; i < 8; i++) {
                const ulonglong2 w = *(const ulonglong2*)(wb + i * 4);
                FMA2(ac[2 * i + 0], hd, w.x);
                FMA2(ac[2 * i + 1], hd, w.y);
            }
        }
        const float prj = sm[O_PROJ + px];
        const int row  = it * 4 + (px >> 5);
        const int gcol = j0 + (px & 31);
        #pragma unroll
        for (int i = 0; i < 16; i++) {
            unsigned u0, u1;
            UPK2(u0, u1, ac[i]);
            #pragma unroll
            for (int s2 = 0; s2 < 2; s2++) {
                const int c = c0 + 2 * i + s2;
                float al = __uint_as_float(s2 ? u1 : u0) + sm[O_ALB + c];
                float y  = (al * prj - sm[O_BNM + c]) * sm[O_BNI + c] + sm[O_BNB + c];
                float r  = y * __fdividef(1.f, 1.f + __expf(-y));
                out[((bz * 64 + c) * IMG + row) * IMG + gcol] = r;
            }
        }
    }
}

extern "C" void kernel_launch(void* const* d_in, const int* in_sizes, int n_in,
                              void* d_out, int out_size) {
    cudaFuncSetAttribute(sac_kernel, cudaFuncAttributeMaxDynamicSharedMemorySize,
                         SMEM_F * sizeof(float));
    dim3 grid(3, 24, 4);
    sac_kernel<<<grid, NT, SMEM_F * sizeof(float)>>>(
        (const float*)d_in[0],  (const float*)d_in[1], (const float*)d_in[2],
        (const float*)d_in[3],  (const float*)d_in[4], (const float*)d_in[5],
        (const float*)d_in[6],  (const float*)d_in[7], (const float*)d_in[8],
        (const float*)d_in[9],  (const float*)d_in[10], (float*)d_out);
}

// round 12
// speedup vs baseline: 1.3080x; 1.0045x over previous
#include <cuda_runtime.h>
#include <math.h>

#define IMG 96
#define NT  256

// ---- smem layout (float word offsets) ----
#define O_XS    0                 // xs: 32ch x 6 rows x 36 cols, ch stride 217
#define XS_CS   217
#define XS_RS   36
#define O_PHI   6944              // phi chunk: 144 k-rows x 64 d; later alphaT (64x68)
#define O_HS    16160             // h: 128 px x 66
#define HS_ST   66
#define O_ST    24608             // stats: 128 x 6 ([5] = phi_b dot patch)
#define O_PROJ  25376
#define O_FC1W  25504
#define O_FC1B  25824
#define O_PHIB  25888
#define O_ALB   26176
#define O_BNI   26240
#define O_BNM   26304
#define O_BNB   26368
#define SMEM_F  26432             // 105728 B -> 2 blocks/SM, single wave @ 288 blocks

#define PK2(d, lo, hi) asm("mov.b64 %0, {%1, %2};" : "=l"(d) : "r"(lo), "r"(hi))
#define UPK2(lo, hi, v) asm("mov.b64 {%0, %1}, %2;" : "=r"(lo), "=r"(hi) : "l"(v))
#define FMA2(d, a, b) asm("fma.rn.f32x2 %0, %1, %2, %3;" : "=l"(d) : "l"(a), "l"(b), "l"(d))

__global__ __launch_bounds__(NT, 2) void sac_kernel(
    const float* __restrict__ x,       const float* __restrict__ fc1_w,
    const float* __restrict__ fc1_b,   const float* __restrict__ alpha_w,
    const float* __restrict__ alpha_b, const float* __restrict__ phi_w,
    const float* __restrict__ phi_b,   const float* __restrict__ bn_g,
    const float* __restrict__ bn_b,    const float* __restrict__ bn_m,
    const float* __restrict__ bn_v,    float* __restrict__ out)
{
    extern __shared__ float sm[];
    const int t  = threadIdx.x;
    const int jt = blockIdx.x;          // 3 col tiles of 32
    const int it = blockIdx.y;          // 24 row tiles of 4
    const int bz = blockIdx.z;
    const int j0 = jt * 32;
    float* xs = sm + O_XS;

    // ---------------- Phase 0: stage ----------------
    for (int idx = t; idx < 32 * 216; idx += NT) {
        int c = idx / 216, rem = idx - c * 216;
        int r = rem / 36, col = rem - r * 36;
        int gr = it * 4 - 1 + r, gc = j0 - 1 + col;
        float v = 0.f;
        if (col < 34 && (unsigned)gr < IMG && (unsigned)gc < IMG)
            v = x[((bz * 32 + c) * IMG + gr) * IMG + gc];
        xs[c * XS_CS + r * XS_RS + col] = v;
    }
    {   // phi k-rows [0,144)
        const float4* pw4 = (const float4*)phi_w;
        float4* ps4 = (float4*)(sm + O_PHI);
        for (int idx = t; idx < 2304; idx += NT) ps4[idx] = pw4[idx];
    }
    for (int idx = t; idx < 320; idx += NT) sm[O_FC1W + idx] = fc1_w[idx];
    for (int idx = t; idx < 288; idx += NT) sm[O_PHIB + idx] = phi_b[idx];
    if (t < 64) {
        sm[O_FC1B + t] = fc1_b[t];
        sm[O_ALB  + t] = alpha_b[t];
        sm[O_BNI  + t] = bn_g[t] * rsqrtf(bn_v[t] + 1e-5f);
        sm[O_BNM  + t] = bn_m[t];
        sm[O_BNB  + t] = bn_b[t];
    }
    __syncthreads();

    // ---------------- Phase A: stats, 8 thr/px, 4 passes of 32 px ----------------
    {
        const int sub = t & 7;
        #pragma unroll 1
        for (int p4 = 0; p4 < 4; p4++) {
            const int pxl = p4 * 32 + (t >> 3);
            const int ra = pxl >> 5, ca = pxl & 31;
            float v[36];
            float s0 = 0.f, mn = 3.4e38f, mx = -3.4e38f, pb = 0.f;
            #pragma unroll
            for (int cc = 0; cc < 4; cc++) {
                const int c = sub + cc * 8;
                const float* xb = xs + c * XS_CS + ra * XS_RS + ca;
                const float* pbb = sm + O_PHIB + c * 9;
                #pragma unroll
                for (int kh = 0; kh < 3; kh++)
                    #pragma unroll
                    for (int kw = 0; kw < 3; kw++) {
                        float val = xb[kh * XS_RS + kw];
                        v[cc * 9 + kh * 3 + kw] = val;
                        s0 += val;
                        mn = fminf(mn, val);
                        mx = fmaxf(mx, val);
                        pb += pbb[kh * 3 + kw] * val;
                    }
            }
            #pragma unroll
            for (int m = 1; m < 8; m <<= 1) {
                s0 += __shfl_xor_sync(0xffffffffu, s0, m);
                pb += __shfl_xor_sync(0xffffffffu, pb, m);
                mn = fminf(mn, __shfl_xor_sync(0xffffffffu, mn, m));
                mx = fmaxf(mx, __shfl_xor_sync(0xffffffffu, mx, m));
            }
            const float mu  = s0 * (1.f / 288.f);
            const float rng = mx - mn + 1e-6f;
            const float s15 = __fdiv_rn(15.f, rng);
            float sd2 = 0.f;
            unsigned long long hl = 0ull, hh = 0ull;
            #pragma unroll
            for (int i = 0; i < 36; i++) {
                float d = v[i] - mu;
                sd2 += d * d;
                float dmn = v[i] - mn;
                float y = dmn * s15;
                int b = (int)y;
                float fb = (float)b;
                float eps = y * 1.2e-6f + 1e-35f;
                if (y - fb < eps || (fb + 1.0f) - y < eps)
                    b = (int)(__fdiv_rn(dmn, rng) * 15.0f);   // exact reference path
                b = min(b, 15);
                unsigned long long one = 1ull << ((b & 7) * 8);
                hl += (b < 8) ? one : 0ull;
                hh += (b < 8) ? 0ull : one;
            }
            #pragma unroll
            for (int m = 1; m < 8; m <<= 1) sd2 += __shfl_xor_sync(0xffffffffu, sd2, m);
            const float var   = sd2 * (1.f / 288.f);
            const float sigma = __fsqrt_rn(var + 1e-6f);
            const float zinv  = __fdiv_rn(1.f, sigma + 1e-6f);
            float s3 = 0.f, s4 = 0.f;
            #pragma unroll
            for (int i = 0; i < 36; i++) {
                float z = (v[i] - mu) * zinv, z2 = z * z;
                s3 += z2 * z;
                s4 += z2 * z2;
            }
            const unsigned long long M8 = 0x00FF00FF00FF00FFull;
            unsigned long long wl0 = hl & M8, wl1 = (hl >> 8) & M8;
            unsigned long long wh0 = hh & M8, wh1 = (hh >> 8) & M8;
            #pragma unroll
            for (int m = 1; m < 8; m <<= 1) {
                s3  += __shfl_xor_sync(0xffffffffu, s3, m);
                s4  += __shfl_xor_sync(0xffffffffu, s4, m);
                wl0 += __shfl_xor_sync(0xffffffffu, wl0, m);
                wl1 += __shfl_xor_sync(0xffffffffu, wl1, m);
                wh0 += __shfl_xor_sync(0xffffffffu, wh0, m);
                wh1 += __shfl_xor_sync(0xffffffffu, wh1, m);
            }
            // entropy: 2 bins per lane
            unsigned long long wa = (sub & 2) ? wl1 : wl0;
            unsigned long long wb = (sub & 2) ? wh1 : wh0;
            unsigned long long w  = (sub & 4) ? wb : wa;
            unsigned c0 = (unsigned)(w >> ((sub & 1) * 32)) & 0xFFFFu;
            unsigned c1 = (unsigned)(w >> ((sub & 1) * 32 + 16)) & 0xFFFFu;
            float p0 = (float)c0 * (1.f / 288.f), p1 = (float)c1 * (1.f / 288.f);
            float ent = -(p0 * __logf(p0 + 1e-9f) + p1 * __logf(p1 + 1e-9f));
            #pragma unroll
            for (int m = 1; m < 8; m <<= 1) ent += __shfl_xor_sync(0xffffffffu, ent, m);
            if (sub == 0) {
                sm[O_ST + pxl * 6 + 0] = mu;
                sm[O_ST + pxl * 6 + 1] = sigma;
                sm[O_ST + pxl * 6 + 2] = s3 * (1.f / 288.f);
                sm[O_ST + pxl * 6 + 3] = s4 * (1.f / 288.f) - 3.0f;
                sm[O_ST + pxl * 6 + 4] = ent;
                sm[O_ST + pxl * 6 + 5] = pb;
            }
        }
    }
    __syncthreads();

    // ---------------- Phase B: h = relu(fc1(s)), 2 thr/px ----------------
    {
        const int px = t >> 1, db = (t & 1) * 32;
        const float s0 = sm[O_ST + px * 6 + 0], s1 = sm[O_ST + px * 6 + 1],
                    s2 = sm[O_ST + px * 6 + 2], s3 = sm[O_ST + px * 6 + 3],
                    s4 = sm[O_ST + px * 6 + 4];
        #pragma unroll 8
        for (int dd = 0; dd < 32; dd++) {
            int d = db + dd;
            const float* wp = sm + O_FC1W + d * 5;
            float a = sm[O_FC1B + d] + s0 * wp[0] + s1 * wp[1] + s2 * wp[2]
                      + s3 * wp[3] + s4 * wp[4];
            sm[O_HS + px * HS_ST + d] = fmaxf(a, 0.f);
        }
    }
    __syncthreads();

    // ---------------- Phase C: q-GEMM 128px x 64d x 288k, d-pair acc ----------------
    // lane dg owns 4 d (2 natural u64 B pairs, zero B packs); A dup'd in regs
    const int dg = t & 15, pg = t >> 4;
    const int d0 = dg * 4;
    const int rr = pg >> 2, col0 = (pg & 3) * 8;   // 8 px: cols col0..col0+7, row rr
    unsigned long long acc[2][8];
    #pragma unroll
    for (int q = 0; q < 2; q++)
        #pragma unroll
        for (int p = 0; p < 8; p++) acc[q][p] = 0ull;

    {
        const float* xb = xs + rr * XS_RS + col0;
        #pragma unroll 1
        for (int c = 0; c < 16; c++) {
            #pragma unroll
            for (int kh = 0; kh < 3; kh++) {
                const float* xr = xb + c * XS_CS + kh * XS_RS;
                unsigned long long ad[10];
                #pragma unroll
                for (int j = 0; j < 10; j++) {
                    unsigned u = __float_as_uint(xr[j]);
                    PK2(ad[j], u, u);
                }
                const float* bb = sm + O_PHI + (c * 9 + kh * 3) * 64 + d0;
                #pragma unroll
                for (int kw = 0; kw < 3; kw++) {
                    const ulonglong2 b = *(const ulonglong2*)(bb + kw * 64);
                    #pragma unroll
                    for (int p = 0; p < 8; p++) {
                        FMA2(acc[0][p], ad[p + kw], b.x);
                        FMA2(acc[1][p], ad[p + kw], b.y);
                    }
                }
            }
        }
    }
    __syncthreads();
    {   // restage phi k-rows [144,288)
        const float4* pw4 = (const float4*)phi_w;
        float4* ps4 = (float4*)(sm + O_PHI);
        for (int idx = t; idx < 2304; idx += NT) ps4[idx] = pw4[2304 + idx];
    }
    __syncthreads();
    {
        const float* xb = xs + rr * XS_RS + col0;
        #pragma unroll 1
        for (int c = 0; c < 16; c++) {
            #pragma unroll
            for (int kh = 0; kh < 3; kh++) {
                const float* xr = xb + (c + 16) * XS_CS + kh * XS_RS;
                unsigned long long ad[10];
                #pragma unroll
                for (int j = 0; j < 10; j++) {
                    unsigned u = __float_as_uint(xr[j]);
                    PK2(ad[j], u, u);
                }
                const float* bb = sm + O_PHI + (c * 9 + kh * 3) * 64 + d0;
                #pragma unroll
                for (int kw = 0; kw < 3; kw++) {
                    const ulonglong2 b = *(const ulonglong2*)(bb + kw * 64);
                    #pragma unroll
                    for (int p = 0; p < 8; p++) {
                        FMA2(acc[0][p], ad[p + kw], b.x);
                        FMA2(acc[1][p], ad[p + kw], b.y);
                    }
                }
            }
        }
    }
    // epilogue: proj = h.q + phi_b.patch (16-lane reduce over dg)
    {
        #pragma unroll
        for (int p = 0; p < 8; p++) {
            const int pxl = rr * 32 + col0 + p;
            const unsigned long long h0 = *(const unsigned long long*)
                (sm + O_HS + pxl * HS_ST + d0);
            const unsigned long long h1 = *(const unsigned long long*)
                (sm + O_HS + pxl * HS_ST + d0 + 2);
            unsigned long long s = 0ull;
            FMA2(s, acc[0][p], h0);
            FMA2(s, acc[1][p], h1);
            unsigned lo, hi;
            UPK2(lo, hi, s);
            float part = __uint_as_float(lo) + __uint_as_float(hi);
            #pragma unroll
            for (int m = 1; m < 16; m <<= 1)
                part += __shfl_xor_sync(0xffffffffu, part, m);
            if (dg == 0) sm[O_PROJ + pxl] = part + sm[O_ST + pxl * 6 + 5];
        }
    }
    __syncthreads();

    // stage alpha_w^T into dead phi area (stride 68)
    for (int idx = t; idx < 64 * 64; idx += NT) {
        int c = idx >> 6, d = idx & 63;
        sm[O_PHI + d * 68 + c] = alpha_w[idx];
    }
    __syncthreads();

    // ---------------- Phase D: alpha GEMV (c-pair f32x2) + BN + SiLU ----------------
    {
        const int px = t >> 1, cq = t & 1;
        const int c0 = cq * 32;                    // 32 c = 16 pairs
        unsigned long long ac[16];
        #pragma unroll
        for (int i = 0; i < 16; i++) ac[i] = 0ull;
        #pragma unroll 4
        for (int d = 0; d < 64; d++) {
            float h = sm[O_HS + px * HS_ST + d];
            unsigned long long hd;
            unsigned hu = __float_as_uint(h);
            PK2(hd, hu, hu);
            const float* wb = sm + O_PHI + d * 68 + c0;
            #pragma unroll
            for (int i = 0; i < 8; i++) {
                const ulonglong2 w = *(const ulonglong2*)(wb + i * 4);
                FMA2(ac[2 * i + 0], hd, w.x);
                FMA2(ac[2 * i + 1], hd, w.y);
            }
        }
        const float prj = sm[O_PROJ + px];
        const int row  = it * 4 + (px >> 5);
        const int gcol = j0 + (px & 31);
        #pragma unroll
        for (int i = 0; i < 16; i++) {
            unsigned u0, u1;
            UPK2(u0, u1, ac[i]);
            #pragma unroll
            for (int s2 = 0; s2 < 2; s2++) {
                const int c = c0 + 2 * i + s2;
                float al = __uint_as_float(s2 ? u1 : u0) + sm[O_ALB + c];
                float y  = (al * prj - sm[O_BNM + c]) * sm[O_BNI + c] + sm[O_BNB + c];
                float r  = y * __fdividef(1.f, 1.f + __expf(-y));
                out[((bz * 64 + c) * IMG + row) * IMG + gcol] = r;
            }
        }
    }
}

extern "C" void kernel_launch(void* const* d_in, const int* in_sizes, int n_in,
                              void* d_out, int out_size) {
    cudaFuncSetAttribute(sac_kernel, cudaFuncAttributeMaxDynamicSharedMemorySize,
                         SMEM_F * sizeof(float));
    dim3 grid(3, 24, 4);
    sac_kernel<<<grid, NT, SMEM_F * sizeof(float)>>>(
        (const float*)d_in[0],  (const float*)d_in[1], (const float*)d_in[2],
        (const float*)d_in[3],  (const float*)d_in[4], (const float*)d_in[5],
        (const float*)d_in[6],  (const float*)d_in[7], (const float*)d_in[8],
        (const float*)d_in[9],  (const float*)d_in[10], (float*)d_out);
}

// round 13
// speedup vs baseline: 1.3139x; 1.0046x over previous
#include <cuda_runtime.h>
#include <math.h>

#define IMG 96
#define NT  256

// ---- smem layout (float word offsets) ----
#define O_XS    0                 // xs: 32ch x 6 rows x 36 cols, ch stride 217
#define XS_CS   217
#define XS_RS   36
#define O_PHI   6944              // phi chunk: 144 k-rows x 64 d; later alphaT (64x68)
#define O_HS    16160             // h: 128 px x 66
#define HS_ST   66
#define O_ST    24608             // stats: 128 x 6 ([5] = phi_b dot patch)
#define O_PROJ  25376
#define O_FC1W  25504
#define O_FC1B  25824
#define O_PHIB  25888
#define O_ALB   26176
#define O_BNI   26240
#define O_BNM   26304
#define O_BNB   26368
#define SMEM_F  26432             // 105728 B -> 2 blocks/SM, single wave @ 288 blocks

#define PK2(d, lo, hi) asm("mov.b64 %0, {%1, %2};" : "=l"(d) : "r"(lo), "r"(hi))
#define UPK2(lo, hi, v) asm("mov.b64 {%0, %1}, %2;" : "=r"(lo), "=r"(hi) : "l"(v))
#define FMA2(d, a, b) asm("fma.rn.f32x2 %0, %1, %2, %3;" : "=l"(d) : "l"(a), "l"(b), "l"(d))

__global__ __launch_bounds__(NT, 2) void sac_kernel(
    const float* __restrict__ x,       const float* __restrict__ fc1_w,
    const float* __restrict__ fc1_b,   const float* __restrict__ alpha_w,
    const float* __restrict__ alpha_b, const float* __restrict__ phi_w,
    const float* __restrict__ phi_b,   const float* __restrict__ bn_g,
    const float* __restrict__ bn_b,    const float* __restrict__ bn_m,
    const float* __restrict__ bn_v,    float* __restrict__ out)
{
    extern __shared__ float sm[];
    const int t  = threadIdx.x;
    const int jt = blockIdx.x;          // 3 col tiles of 32
    const int it = blockIdx.y;          // 24 row tiles of 4
    const int bz = blockIdx.z;
    const int j0 = jt * 32;
    float* xs = sm + O_XS;

    // ---------------- Phase 0: stage ----------------
    for (int idx = t; idx < 32 * 216; idx += NT) {
        int c = idx / 216, rem = idx - c * 216;
        int r = rem / 36, col = rem - r * 36;
        int gr = it * 4 - 1 + r, gc = j0 - 1 + col;
        float v = 0.f;
        if (col < 34 && (unsigned)gr < IMG && (unsigned)gc < IMG)
            v = x[((bz * 32 + c) * IMG + gr) * IMG + gc];
        xs[c * XS_CS + r * XS_RS + col] = v;
    }
    {   // phi k-rows [0,144)
        const float4* pw4 = (const float4*)phi_w;
        float4* ps4 = (float4*)(sm + O_PHI);
        for (int idx = t; idx < 2304; idx += NT) ps4[idx] = pw4[idx];
    }
    for (int idx = t; idx < 320; idx += NT) sm[O_FC1W + idx] = fc1_w[idx];
    for (int idx = t; idx < 288; idx += NT) sm[O_PHIB + idx] = phi_b[idx];
    if (t < 64) {
        sm[O_FC1B + t] = fc1_b[t];
        sm[O_ALB  + t] = alpha_b[t];
        sm[O_BNI  + t] = bn_g[t] * rsqrtf(bn_v[t] + 1e-5f);
        sm[O_BNM  + t] = bn_m[t];
        sm[O_BNB  + t] = bn_b[t];
    }
    __syncthreads();

    // ---------------- Phase A: stats, 8 thr/px, 4 passes of 32 px ----------------
    {
        const int sub = t & 7;
        #pragma unroll 1
        for (int p4 = 0; p4 < 4; p4++) {
            const int pxl = p4 * 32 + (t >> 3);
            const int ra = pxl >> 5, ca = pxl & 31;
            float v[36];
            float s0 = 0.f, mn = 3.4e38f, mx = -3.4e38f, pb = 0.f;
            #pragma unroll
            for (int cc = 0; cc < 4; cc++) {
                const int c = sub + cc * 8;
                const float* xb = xs + c * XS_CS + ra * XS_RS + ca;
                const float* pbb = sm + O_PHIB + c * 9;
                #pragma unroll
                for (int kh = 0; kh < 3; kh++)
                    #pragma unroll
                    for (int kw = 0; kw < 3; kw++) {
                        float val = xb[kh * XS_RS + kw];
                        v[cc * 9 + kh * 3 + kw] = val;
                        s0 += val;
                        mn = fminf(mn, val);
                        mx = fmaxf(mx, val);
                        pb += pbb[kh * 3 + kw] * val;
                    }
            }
            #pragma unroll
            for (int m = 1; m < 8; m <<= 1) {
                s0 += __shfl_xor_sync(0xffffffffu, s0, m);
                pb += __shfl_xor_sync(0xffffffffu, pb, m);
                mn = fminf(mn, __shfl_xor_sync(0xffffffffu, mn, m));
                mx = fmaxf(mx, __shfl_xor_sync(0xffffffffu, mx, m));
            }
            const float mu  = s0 * (1.f / 288.f);
            const float rng = mx - mn + 1e-6f;
            const float s15 = __fdiv_rn(15.f, rng);
            float sd2 = 0.f;
            unsigned long long hl = 0ull, hh = 0ull;
            #pragma unroll
            for (int i = 0; i < 36; i++) {
                float d = v[i] - mu;
                sd2 += d * d;
                float dmn = v[i] - mn;
                float y = dmn * s15;
                int b = (int)y;
                float fb = (float)b;
                float eps = y * 1.2e-6f + 1e-35f;
                if (y - fb < eps || (fb + 1.0f) - y < eps)
                    b = (int)(__fdiv_rn(dmn, rng) * 15.0f);   // exact reference path
                b = min(b, 15);
                unsigned long long one = 1ull << ((b & 7) * 8);
                hl += (b < 8) ? one : 0ull;
                hh += (b < 8) ? 0ull : one;
            }
            #pragma unroll
            for (int m = 1; m < 8; m <<= 1) sd2 += __shfl_xor_sync(0xffffffffu, sd2, m);
            const float var   = sd2 * (1.f / 288.f);
            const float sigma = __fsqrt_rn(var + 1e-6f);
            const float zinv  = __fdiv_rn(1.f, sigma + 1e-6f);
            float s3 = 0.f, s4 = 0.f;
            #pragma unroll
            for (int i = 0; i < 36; i++) {
                float z = (v[i] - mu) * zinv, z2 = z * z;
                s3 += z2 * z;
                s4 += z2 * z2;
            }
            const unsigned long long M8 = 0x00FF00FF00FF00FFull;
            unsigned long long wl0 = hl & M8, wl1 = (hl >> 8) & M8;
            unsigned long long wh0 = hh & M8, wh1 = (hh >> 8) & M8;
            #pragma unroll
            for (int m = 1; m < 8; m <<= 1) {
                s3  += __shfl_xor_sync(0xffffffffu, s3, m);
                s4  += __shfl_xor_sync(0xffffffffu, s4, m);
                wl0 += __shfl_xor_sync(0xffffffffu, wl0, m);
                wl1 += __shfl_xor_sync(0xffffffffu, wl1, m);
                wh0 += __shfl_xor_sync(0xffffffffu, wh0, m);
                wh1 += __shfl_xor_sync(0xffffffffu, wh1, m);
            }
            // entropy: 2 bins per lane
            unsigned long long wa = (sub & 2) ? wl1 : wl0;
            unsigned long long wb = (sub & 2) ? wh1 : wh0;
            unsigned long long w  = (sub & 4) ? wb : wa;
            unsigned c0 = (unsigned)(w >> ((sub & 1) * 32)) & 0xFFFFu;
            unsigned c1 = (unsigned)(w >> ((sub & 1) * 32 + 16)) & 0xFFFFu;
            float p0 = (float)c0 * (1.f / 288.f), p1 = (float)c1 * (1.f / 288.f);
            float ent = -(p0 * __logf(p0 + 1e-9f) + p1 * __logf(p1 + 1e-9f));
            #pragma unroll
            for (int m = 1; m < 8; m <<= 1) ent += __shfl_xor_sync(0xffffffffu, ent, m);
            if (sub == 0) {
                sm[O_ST + pxl * 6 + 0] = mu;
                sm[O_ST + pxl * 6 + 1] = sigma;
                sm[O_ST + pxl * 6 + 2] = s3 * (1.f / 288.f);
                sm[O_ST + pxl * 6 + 3] = s4 * (1.f / 288.f) - 3.0f;
                sm[O_ST + pxl * 6 + 4] = ent;
                sm[O_ST + pxl * 6 + 5] = pb;
            }
        }
    }
    __syncthreads();

    // ---------------- Phase B: h = relu(fc1(s)), 2 thr/px ----------------
    {
        const int px = t >> 1, db = (t & 1) * 32;
        const float s0 = sm[O_ST + px * 6 + 0], s1 = sm[O_ST + px * 6 + 1],
                    s2 = sm[O_ST + px * 6 + 2], s3 = sm[O_ST + px * 6 + 3],
                    s4 = sm[O_ST + px * 6 + 4];
        #pragma unroll 8
        for (int dd = 0; dd < 32; dd++) {
            int d = db + dd;
            const float* wp = sm + O_FC1W + d * 5;
            float a = sm[O_FC1B + d] + s0 * wp[0] + s1 * wp[1] + s2 * wp[2]
                      + s3 * wp[3] + s4 * wp[4];
            sm[O_HS + px * HS_ST + d] = fmaxf(a, 0.f);
        }
    }
    __syncthreads();

    // ---------------- Phase C: q-GEMM 128px x 64d x 288k, d-pair acc ----------------
    // lane dg owns 4 d (2 natural u64 B pairs, zero B packs); A dup'd in regs
    const int dg = t & 15, pg = t >> 4;
    const int d0 = dg * 4;
    const int rr = pg >> 2, col0 = (pg & 3) * 8;   // 8 px: cols col0..col0+7, row rr
    unsigned long long acc[2][8];
    #pragma unroll
    for (int q = 0; q < 2; q++)
        #pragma unroll
        for (int p = 0; p < 8; p++) acc[q][p] = 0ull;

    {
        const float* xb = xs + rr * XS_RS + col0;
        #pragma unroll 1
        for (int c = 0; c < 16; c++) {
            #pragma unroll
            for (int kh = 0; kh < 3; kh++) {
                const float* xr = xb + c * XS_CS + kh * XS_RS;
                unsigned long long ad[10];
                #pragma unroll
                for (int j = 0; j < 10; j++) {
                    unsigned u = __float_as_uint(xr[j]);
                    PK2(ad[j], u, u);
                }
                const float* bb = sm + O_PHI + (c * 9 + kh * 3) * 64 + d0;
                #pragma unroll
                for (int kw = 0; kw < 3; kw++) {
                    const ulonglong2 b = *(const ulonglong2*)(bb + kw * 64);
                    #pragma unroll
                    for (int p = 0; p < 8; p++) {
                        FMA2(acc[0][p], ad[p + kw], b.x);
                        FMA2(acc[1][p], ad[p + kw], b.y);
                    }
                }
            }
        }
    }
    __syncthreads();
    {   // restage phi k-rows [144,288)
        const float4* pw4 = (const float4*)phi_w;
        float4* ps4 = (float4*)(sm + O_PHI);
        for (int idx = t; idx < 2304; idx += NT) ps4[idx] = pw4[2304 + idx];
    }
    __syncthreads();
    {
        const float* xb = xs + rr * XS_RS + col0;
        #pragma unroll 1
        for (int c = 0; c < 16; c++) {
            #pragma unroll
            for (int kh = 0; kh < 3; kh++) {
                const float* xr = xb + (c + 16) * XS_CS + kh * XS_RS;
                unsigned long long ad[10];
                #pragma unroll
                for (int j = 0; j < 10; j++) {
                    unsigned u = __float_as_uint(xr[j]);
                    PK2(ad[j], u, u);
                }
                const float* bb = sm + O_PHI + (c * 9 + kh * 3) * 64 + d0;
                #pragma unroll
                for (int kw = 0; kw < 3; kw++) {
                    const ulonglong2 b = *(const ulonglong2*)(bb + kw * 64);
                    #pragma unroll
                    for (int p = 0; p < 8; p++) {
                        FMA2(acc[0][p], ad[p + kw], b.x);
                        FMA2(acc[1][p], ad[p + kw], b.y);
                    }
                }
            }
        }
    }
    // epilogue: proj = h.q + phi_b.patch (16-lane reduce over dg)
    {
        #pragma unroll
        for (int p = 0; p < 8; p++) {
            const int pxl = rr * 32 + col0 + p;
            const unsigned long long h0 = *(const unsigned long long*)
                (sm + O_HS + pxl * HS_ST + d0);
            const unsigned long long h1 = *(const unsigned long long*)
                (sm + O_HS + pxl * HS_ST + d0 + 2);
            unsigned long long s = 0ull;
            FMA2(s, acc[0][p], h0);
            FMA2(s, acc[1][p], h1);
            unsigned lo, hi;
            UPK2(lo, hi, s);
            float part = __uint_as_float(lo) + __uint_as_float(hi);
            #pragma unroll
            for (int m = 1; m < 16; m <<= 1)
                part += __shfl_xor_sync(0xffffffffu, part, m);
            if (dg == 0) sm[O_PROJ + pxl] = part + sm[O_ST + pxl * 6 + 5];
        }
    }
    __syncthreads();

    // stage alpha_w^T into dead phi area (stride 68)
    for (int idx = t; idx < 64 * 64; idx += NT) {
        int c = idx >> 6, d = idx & 63;
        sm[O_PHI + d * 68 + c] = alpha_w[idx];
    }
    __syncthreads();

    // ---------------- Phase D: alpha GEMV (c-pair f32x2) + BN + SiLU ----------------
    {
        const int px = t >> 1, cq = t & 1;
        const int c0 = cq * 32;                    // 32 c = 16 pairs
        unsigned long long ac[16];
        #pragma unroll
        for (int i = 0; i < 16; i++) ac[i] = 0ull;
        #pragma unroll 4
        for (int d = 0; d < 64; d++) {
            float h = sm[O_HS + px * HS_ST + d];
            unsigned long long hd;
            unsigned hu = __float_as_uint(h);
            PK2(hd, hu, hu);
            const float* wb = sm + O_PHI + d * 68 + c0;
            #pragma unroll
            for (int i = 0; i < 8; i++) {
                const ulonglong2 w = *(const ulonglong2*)(wb + i * 4);
                FMA2(ac[2 * i + 0], hd, w.x);
                FMA2(ac[2 * i + 1], hd, w.y);
            }
        }
        const float prj = sm[O_PROJ + px];
        const int row  = it * 4 + (px >> 5);
        const int gcol = j0 + (px & 31);
        #pragma unroll
        for (int i = 0; i < 16; i++) {
            unsigned u0, u1;
            UPK2(u0, u1, ac[i]);
            #pragma unroll
            for (int s2 = 0; s2 < 2; s2++) {
                const int c = c0 + 2 * i + s2;
                float al = __uint_as_float(s2 ? u1 : u0) + sm[O_ALB + c];
                float y  = (al * prj - sm[O_BNM + c]) * sm[O_BNI + c] + sm[O_BNB + c];
                float r  = y * __fdividef(1.f, 1.f + __expf(-y));
                out[((bz * 64 + c) * IMG + row) * IMG + gcol] = r;
            }
        }
    }
}

extern "C" void kernel_launch(void* const* d_in, const int* in_sizes, int n_in,
                              void* d_out, int out_size) {
    cudaFuncSetAttribute(sac_kernel, cudaFuncAttributeMaxDynamicSharedMemorySize,
                         SMEM_F * sizeof(float));
    dim3 grid(3, 24, 4);
    sac_kernel<<<grid, NT, SMEM_F * sizeof(float)>>>(
        (const float*)d_in[0],  (const float*)d_in[1], (const float*)d_in[2],
        (const float*)d_in[3],  (const float*)d_in[4], (const float*)d_in[5],
        (const float*)d_in[6],  (const float*)d_in[7], (const float*)d_in[8],
        (const float*)d_in[9],  (const float*)d_in[10], (float*)d_out);
}